// round 6
// baseline (speedup 1.0000x reference)
#include <cuda_runtime.h>
#include <cuda_bf16.h>

// loss_i = (label_i == label[N-1]) ? d2 : max(0, MARGIN - d2)
// d2 = squared euclidean distance to coords[N-1], D=3. Output: sum over i.
//
// Single-launch design: last-block-done pattern with __device__ scratch
// (no cudaMalloc, no second kernel, graph-capturable). The finishing CTA
// writes d_out and resets the globals so every graph replay is identical.

#define MARGIN 500.0f
#define TPB 256

__device__ float        g_accum = 0.0f;
__device__ unsigned int g_count = 0u;

__global__ __launch_bounds__(TPB)
void contrastive_last_anchor_kernel(const int* __restrict__ labels,
                                    const float* __restrict__ coords,
                                    float* __restrict__ out,
                                    int n)
{
    const int i = blockIdx.x * TPB + threadIdx.x;

    // Anchor = last element. Same 2 cache lines for all threads -> L1 broadcast.
    const int   al = labels[n - 1];
    const float ax = coords[3 * (n - 1) + 0];
    const float ay = coords[3 * (n - 1) + 1];
    const float az = coords[3 * (n - 1) + 2];

    float v = 0.0f;
    if (i < n) {
        const float dx = ax - coords[3 * i + 0];
        const float dy = ay - coords[3 * i + 1];
        const float dz = az - coords[3 * i + 2];
        const float d2 = fmaf(dx, dx, fmaf(dy, dy, dz * dz));
        v = (labels[i] == al) ? d2 : fmaxf(0.0f, MARGIN - d2);
    }

    // Warp reduce
    #pragma unroll
    for (int o = 16; o > 0; o >>= 1)
        v += __shfl_down_sync(0xFFFFFFFFu, v, o);

    // Block reduce
    __shared__ float s[TPB / 32];
    const int lane = threadIdx.x & 31;
    const int wid  = threadIdx.x >> 5;
    if (lane == 0) s[wid] = v;
    __syncthreads();

    if (wid == 0) {
        v = (lane < TPB / 32) ? s[lane] : 0.0f;
        #pragma unroll
        for (int o = 16; o > 0; o >>= 1)
            v += __shfl_down_sync(0xFFFFFFFFu, v, o);

        if (lane == 0) {
            atomicAdd(&g_accum, v);
            __threadfence();
            const unsigned old = atomicAdd(&g_count, 1u);
            if (old == gridDim.x - 1) {
                // All CTAs' accum atomics are ordered before their count
                // atomics (threadfence above); read via atomic for safety.
                const float total = atomicAdd(&g_accum, 0.0f);
                out[0] = total;
                // Reset for the next graph replay.
                atomicExch(&g_accum, 0.0f);
                atomicExch(&g_count, 0u);
                __threadfence();
            }
        }
    }
}

extern "C" void kernel_launch(void* const* d_in, const int* in_sizes, int n_in,
                              void* d_out, int out_size)
{
    const int*   labels = (const int*)d_in[0];
    const float* coords = (const float*)d_in[1];
    float*       out    = (float*)d_out;
    const int n = in_sizes[0];

    const int blocks = (n + TPB - 1) / TPB;  // 128 for n=32768 -> single wave
    contrastive_last_anchor_kernel<<<blocks, TPB>>>(labels, coords, out, n);
}